// round 3
// baseline (speedup 1.0000x reference)
#include <cuda_runtime.h>

#define H 64
#define KCH 24
#define THREADS 256

__global__ __launch_bounds__(THREADS, 8)
void gauss_scatter_kernel(const float* __restrict__ x,
                          const float* __restrict__ weight,
                          const int*  __restrict__ vis_batch,
                          const int*  __restrict__ vis_kps,
                          int n_vis,
                          float* __restrict__ out)
{
    const int o = blockIdx.x;   // output channel 0..23
    const int b = blockIdx.y;   // batch 0..1023
    const int tid = threadIdx.x;

    __shared__ float map[H * H];           // 16 KB
    __shared__ int   px[KCH], py[KCH];
    __shared__ int   act[KCH];
    __shared__ int   killS[KCH];

    // zero map (16 floats / thread) and kill flags
    #pragma unroll
    for (int i = tid; i < H * H; i += THREADS) map[i] = 0.0f;
    if (tid < KCH) killS[tid] = 0;
    __syncthreads();

    // scan vis list: mark killed keypoints for this batch
    for (int i = tid; i < n_vis; i += THREADS) {
        if (__ldg(&vis_batch[i]) == b) killS[__ldg(&vis_kps[i])] = 1;
    }
    __syncthreads();

    // compute coords + active flags for the 24 keypoints
    if (tid < KCH) {
        float fx = __ldg(&x[((size_t)b * KCH + tid) * 2 + 0]);
        float fy = __ldg(&x[((size_t)b * KCH + tid) * 2 + 1]);
        // match JAX: round(((x + 1) * 0.5) * (H-1)), banker's rounding
        float rx = rintf(((fx + 1.0f) * 0.5f) * (float)(H - 1));
        float ry = rintf(((fy + 1.0f) * 0.5f) * (float)(H - 1));
        int cx = (int)rx;
        int cy = (int)ry;
        bool invalid = (cx < 0) | (cx >= H) | (cy < 0) | (cy >= H);
        if (invalid) { cx = 0; cy = 0; }
        // torch quirk: only place when x-coordinate is nonzero; then kill mask
        int a = (cx != 0) && (!killS[tid]);
        px[tid] = cx; py[tid] = cy; act[tid] = a;
    }
    __syncthreads();

    // scatter taps: 24 points x 25 taps = 600 work items.
    // lax conv is cross-correlation: out[yk+2-dy, xk+2-dx] += w[o,k,dy,dx]
    for (int it = tid; it < KCH * 25; it += THREADS) {
        int k = it / 25;
        if (act[k]) {
            int t  = it - k * 25;
            int dy = t / 5;
            int dx = t - dy * 5;
            int yy = py[k] + 2 - dy;
            int xx = px[k] + 2 - dx;
            if (yy >= 0 && yy < H && xx >= 0 && xx < H) {
                float wv = __ldg(&weight[((size_t)o * KCH + k) * 25 + t]);
                atomicAdd(&map[yy * H + xx], wv);
            }
        }
    }
    __syncthreads();

    // stream out: 4096 floats = 1024 float4, contiguous per (b,o)
    float4* __restrict__ dst = (float4*)(out + ((size_t)b * KCH + o) * (H * H));
    const float4* __restrict__ src = (const float4*)map;
    #pragma unroll
    for (int i = tid; i < (H * H) / 4; i += THREADS) {
        dst[i] = src[i];
    }
}

extern "C" void kernel_launch(void* const* d_in, const int* in_sizes, int n_in,
                              void* d_out, int out_size)
{
    const float* x      = (const float*)d_in[0];
    const float* weight = (const float*)d_in[1];
    const int*   vb     = (const int*)d_in[2];
    const int*   vk     = (const int*)d_in[3];
    float*       out    = (float*)d_out;

    int n_vis = in_sizes[2];
    int B = in_sizes[0] / (KCH * 2);   // 1024

    dim3 grid(KCH, B);
    gauss_scatter_kernel<<<grid, THREADS>>>(x, weight, vb, vk, n_vis, out);
}

// round 4
// speedup vs baseline: 1.2066x; 1.2066x over previous
#include <cuda_runtime.h>

#define H 64
#define KCH 24
#define THREADS 256
#define MAXB 1024

// Packed per-(b,k) point table: bit30 = active, bits[8:14) = y, bits[0:6) = x.
// 0 means inactive. Written by prep_kernel, cleared by kill_kernel, read by main.
__device__ int g_pts[MAXB * KCH];

// ---------------------------------------------------------------------------
// Pre-kernel 1: compute coords + torch-quirk active flag for all (b,k).
// ---------------------------------------------------------------------------
__global__ void prep_kernel(const float* __restrict__ x, int BK)
{
    int i = blockIdx.x * blockDim.x + threadIdx.x;   // i = b*24 + k
    if (i >= BK) return;
    float fx = __ldg(&x[2 * i + 0]);
    float fy = __ldg(&x[2 * i + 1]);
    // match JAX: round(((x+1)*0.5)*(H-1)), banker's rounding
    int cx = (int)rintf(((fx + 1.0f) * 0.5f) * (float)(H - 1));
    int cy = (int)rintf(((fy + 1.0f) * 0.5f) * (float)(H - 1));
    int v = 0;
    // invalid rows -> coords zeroed -> cx==0 -> inactive; quirk: cx!=0 required
    if ((unsigned)cx < (unsigned)H && (unsigned)cy < (unsigned)H && cx != 0)
        v = (1 << 30) | (cy << 8) | cx;
    g_pts[i] = v;
}

// ---------------------------------------------------------------------------
// Pre-kernel 2: kill visibility-masked keypoints (plain store of 0 — idempotent).
// ---------------------------------------------------------------------------
__global__ void kill_kernel(const int* __restrict__ vb, const int* __restrict__ vk, int n)
{
    int i = blockIdx.x * blockDim.x + threadIdx.x;
    if (i < n) g_pts[vb[i] * KCH + vk[i]] = 0;
}

// ---------------------------------------------------------------------------
// Main kernel: one CTA per (o, b). Register accumulation, no smem heatmap.
// ---------------------------------------------------------------------------
__global__ __launch_bounds__(THREADS)
void gauss_gather_kernel(const float* __restrict__ weight, float* __restrict__ out)
{
    const int o   = blockIdx.x;   // output channel
    const int b   = blockIdx.y;   // batch
    const int tid = threadIdx.x;

    __shared__ float w[KCH * 25 + 72];       // +72 pad: speculative-LDS safety
    __shared__ int   cnt[H];                 // points hitting each output row
    __shared__ int   ent[H * KCH];           // per-row entries: (wbase<<8)|xk

    if (tid < H) cnt[tid] = 0;
    __syncthreads();

    // load this channel's 24x5x5 weights (L2-resident after first wave)
    const float* wsrc = weight + (size_t)o * (KCH * 25);
    for (int i = tid; i < KCH * 25; i += THREADS) w[i] = __ldg(&wsrc[i]);

    // warp 0: build per-row hit lists from the precomputed point table.
    // lax conv = cross-correlation: out[yk+2-dy, xk+2-dx] += w[o,k,dy,dx]
    if (tid < KCH) {
        int v = g_pts[b * KCH + tid];
        if (v) {
            int xk = v & 63;
            int yk = (v >> 8) & 63;
            int wb = tid * 25;
            #pragma unroll
            for (int dy = 0; dy < 5; dy++) {
                int r = yk + 2 - dy;
                if ((unsigned)r < (unsigned)H) {
                    int s = atomicAdd(&cnt[r], 1);
                    ent[r * KCH + s] = ((wb + dy * 5) << 8) | xk;
                }
            }
        }
    }
    __syncthreads();

    // Thread -> pixels: 4 groups of 4 consecutive px, groups 1024 px apart.
    // Group i covers row R0 + 16*i, cols c0..c0+3. Every STG.128 below is a
    // fully-coalesced 512B warp transaction.
    const int R0 = tid >> 4;
    const int c0 = (tid & 15) << 2;
    float4* __restrict__ dst =
        (float4*)(out + (((size_t)b * KCH + o) << 12));

    #pragma unroll
    for (int i = 0; i < 4; i++) {
        const int r = R0 + (i << 4);
        const int n = cnt[r];
        float4 a = make_float4(0.f, 0.f, 0.f, 0.f);
        for (int e = 0; e < n; e++) {
            int v  = ent[r * KCH + e];
            int xk = v & 255;
            int wb = v >> 8;
            int d0 = xk + 2 - c0;          // dx for col c0; col c0+j -> d0-j
            if ((unsigned)(d0    ) <= 4u) a.x += w[wb + d0];
            if ((unsigned)(d0 - 1) <= 4u) a.y += w[wb + d0 - 1];
            if ((unsigned)(d0 - 2) <= 4u) a.z += w[wb + d0 - 2];
            if ((unsigned)(d0 - 3) <= 4u) a.w += w[wb + d0 - 3];
        }
        dst[(i << 8) + tid] = a;           // float4 index = i*256 + tid
    }
}

extern "C" void kernel_launch(void* const* d_in, const int* in_sizes, int n_in,
                              void* d_out, int out_size)
{
    const float* x      = (const float*)d_in[0];
    const float* weight = (const float*)d_in[1];
    const int*   vb     = (const int*)d_in[2];
    const int*   vk     = (const int*)d_in[3];
    float*       out    = (float*)d_out;

    int n_vis = in_sizes[2];
    int B     = in_sizes[0] / (KCH * 2);        // 1024
    int BK    = B * KCH;

    prep_kernel<<<(BK + 255) / 256, 256>>>(x, BK);
    kill_kernel<<<(n_vis + 255) / 256, 256>>>(vb, vk, n_vis);

    dim3 grid(KCH, B);
    gauss_gather_kernel<<<grid, THREADS>>>(weight, out);
}

// round 7
// speedup vs baseline: 1.2374x; 1.0256x over previous
#include <cuda_runtime.h>

#define H 64
#define KCH 24
#define THREADS 256

// ---------------------------------------------------------------------------
// Single fused kernel: one CTA per (o, b).
//  - inlines coord computation, torch quirk, invalid masking, vis-kill scan
//  - builds per-row point lists in smem
//  - register-accumulates 16 px/thread, stores 4 coalesced float4 (streaming)
// ---------------------------------------------------------------------------
__global__ __launch_bounds__(THREADS)
void gauss_fused_kernel(const float* __restrict__ x,
                        const float* __restrict__ weight,
                        const int*  __restrict__ vis_batch,
                        const int*  __restrict__ vis_kps,
                        int n_vis,
                        float* __restrict__ out)
{
    const int o   = blockIdx.x;   // output channel 0..23
    const int b   = blockIdx.y;   // batch 0..1023
    const int tid = threadIdx.x;

    __shared__ float w[KCH * 25 + 72];   // +72 pad (speculative-LDS safety)
    __shared__ int   cnt[H];             // points hitting each output row
    __shared__ int   ent[H * KCH];       // per-row entries: (wbase<<8)|xk
    __shared__ int   killS[KCH];

    if (tid < H)   cnt[tid]  = 0;
    if (tid < KCH) killS[tid] = 0;
    __syncthreads();

    // weights for this channel: 600 floats = 150 float4 (L2-resident)
    if (tid < 150) {
        ((float4*)w)[tid] = __ldg(&((const float4*)(weight + (size_t)o * (KCH * 25)))[tid]);
    }

    // vis-kill scan: 256 entries, 1 per thread (1KB tables, L2 hits)
    for (int i = tid; i < n_vis; i += THREADS) {
        if (__ldg(&vis_batch[i]) == b) killS[__ldg(&vis_kps[i])] = 1;
    }
    __syncthreads();

    // coords + per-row hit lists (lax conv = cross-correlation:
    // out[yk+2-dy, xk+2-dx] += w[o,k,dy,dx])
    if (tid < KCH) {
        float fx = __ldg(&x[((size_t)b * KCH + tid) * 2 + 0]);
        float fy = __ldg(&x[((size_t)b * KCH + tid) * 2 + 1]);
        // match JAX: round(((x+1)*0.5)*(H-1)), banker's rounding
        int cx = (int)rintf(((fx + 1.0f) * 0.5f) * (float)(H - 1));
        int cy = (int)rintf(((fy + 1.0f) * 0.5f) * (float)(H - 1));
        // invalid -> coords zeroed -> cx==0 -> inactive; quirk: cx != 0 required
        bool act = ((unsigned)cx < (unsigned)H) && ((unsigned)cy < (unsigned)H)
                   && (cx != 0) && (!killS[tid]);
        if (act) {
            int wb = tid * 25;
            #pragma unroll
            for (int dy = 0; dy < 5; dy++) {
                int r = cy + 2 - dy;
                if ((unsigned)r < (unsigned)H) {
                    int s = atomicAdd(&cnt[r], 1);
                    ent[r * KCH + s] = ((wb + dy * 5) << 8) | cx;
                }
            }
        }
    }
    __syncthreads();

    // Thread -> pixels: 4 groups of 4 consecutive px, groups 1024 px apart.
    // Group i covers row R0 + 16*i, cols c0..c0+3; each STG.128 below is a
    // fully coalesced 512B warp transaction.
    const int R0 = tid >> 4;
    const int c0 = (tid & 15) << 2;
    float4* __restrict__ dst = (float4*)(out + (((size_t)b * KCH + o) << 12));

    #pragma unroll
    for (int i = 0; i < 4; i++) {
        const int r = R0 + (i << 4);
        const int n = cnt[r];
        float4 a = make_float4(0.f, 0.f, 0.f, 0.f);
        for (int e = 0; e < n; e++) {
            int v  = ent[r * KCH + e];
            int xk = v & 255;
            int wb = v >> 8;
            int d0 = xk + 2 - c0;          // dx for col c0; col c0+j -> d0-j
            if ((unsigned)(d0    ) <= 4u) a.x += w[wb + d0];
            if ((unsigned)(d0 - 1) <= 4u) a.y += w[wb + d0 - 1];
            if ((unsigned)(d0 - 2) <= 4u) a.z += w[wb + d0 - 2];
            if ((unsigned)(d0 - 3) <= 4u) a.w += w[wb + d0 - 3];
        }
        __stcs(&dst[(i << 8) + tid], a);   // streaming store: write-once data
    }
}

extern "C" void kernel_launch(void* const* d_in, const int* in_sizes, int n_in,
                              void* d_out, int out_size)
{
    const float* x      = (const float*)d_in[0];
    const float* weight = (const float*)d_in[1];
    const int*   vb     = (const int*)d_in[2];
    const int*   vk     = (const int*)d_in[3];
    float*       out    = (float*)d_out;

    int n_vis = in_sizes[2];
    int B     = in_sizes[0] / (KCH * 2);   // 1024

    dim3 grid(KCH, B);
    gauss_fused_kernel<<<grid, THREADS>>>(x, weight, vb, vk, n_vis, out);
}